// round 5
// baseline (speedup 1.0000x reference)
#include <cuda_runtime.h>
#include <cuda_bf16.h>
#include <cstdint>

// Problem constants
#define S_TOK   32768
#define HID     1280
#define NHEAD   16
#define DHEAD   80
#define WIN     64
#define NWIN    (S_TOK / WIN)
#define N_QKV   (3 * HID)

// Scratch (__device__ globals per allocation rules)
__device__ float g_xa   [(size_t)S_TOK * HID];    // x RNA-rounded, K-permuted
__device__ float g_qkv  [(size_t)S_TOK * N_QKV];  // qkv output (natural layout)
__device__ float g_attn [(size_t)S_TOK * HID];    // attn out, RNA-rounded, K-permuted
__device__ float g_wqkvT[(size_t)N_QKV * HID];    // qkvW^T [3840,1280], RNA, K-permuted
__device__ float g_wprojT[(size_t)HID * HID];     // projW^T [1280,1280], RNA, K-permuted

__device__ __forceinline__ uint32_t f2tf32(float x) {
    uint32_t r;
    asm volatile("cvt.rna.tf32.f32 %0, %1;" : "=r"(r) : "f"(x));
    return r;
}
__device__ __forceinline__ uint32_t smem_u32(const void* p) {
    uint32_t a;
    asm("{ .reg .u64 t; cvta.to.shared.u64 t, %1; cvt.u32.u64 %0, t; }" : "=r"(a) : "l"(p));
    return a;
}
__device__ __forceinline__ void cp16(uint32_t dst, const void* src) {
    asm volatile("cp.async.cg.shared.global [%0], [%1], 16;" :: "r"(dst), "l"(src) : "memory");
}
#define CP_COMMIT() asm volatile("cp.async.commit_group;" ::: "memory")

// K-permutation within each 32-float block: k -> (k%4)*8 + k/4
__device__ __forceinline__ int permg(int k) {
    return (k & ~31) | ((k & 3) << 3) | ((k & 31) >> 2);
}

// ---------------------------------------------------------------------------
// Legacy-tensor tf32 GEMM: C[M,N] = A[M,1280] @ Bt[N,1280]^T + bias[N]
// A, Bt are RNA-rounded and K-permuted. Block 128x128x32, 8 warps (4M x 2N),
// 3-stage cp.async pipeline, SW128-swizzled tiles, LDS.128 fragment loads.
// ---------------------------------------------------------------------------
#define BM 128
#define BN 128
#define BK 32
#define NSTAGE 3
#define TILE_FLOATS (128 * 32)                   // one operand tile: 16 KB
#define STAGE_FLOATS (2 * TILE_FLOATS)           // 32 KB
#define GEMM_SMEM (NSTAGE * STAGE_FLOATS * 4)    // 98304 B

__global__ __launch_bounds__(256, 2)
void gemm_tc(const float* __restrict__ A, const float* __restrict__ Bt,
             const float* __restrict__ bias, float* __restrict__ C, int N)
{
    extern __shared__ float sm[];
    const int tid  = threadIdx.x;
    const int warp = tid >> 5;
    const int lane = tid & 31;
    const int g = lane >> 2;       // 0..7
    const int t = lane & 3;        // 0..3
    const int wm = (warp & 3) * 32;
    const int wn = (warp >> 2) * 64;
    const int block_m = blockIdx.y * BM;
    const int block_n = blockIdx.x * BN;

    const uint32_t sb = smem_u32(sm);

    float acc[2][8][4];
    #pragma unroll
    for (int i = 0; i < 2; i++)
        #pragma unroll
        for (int j = 0; j < 8; j++)
            #pragma unroll
            for (int r = 0; r < 4; r++) acc[i][j][r] = 0.f;

    const float* Abase = A  + (size_t)block_m * HID;
    const float* Bbase = Bt + (size_t)block_n * HID;

    // fill stage s with K-chunk kidx: A/B each 128 rows x 8 atoms (16B), swizzled
    auto fill = [&](int kidx, int s) {
        const uint32_t sA = sb + s * STAGE_FLOATS * 4;
        const uint32_t sB = sA + TILE_FLOATS * 4;
        const int k0 = kidx * BK;
        #pragma unroll
        for (int ii = 0; ii < 4; ++ii) {
            const int id = tid + ii * 256;
            const int row = id >> 3, c = id & 7;
            cp16(sA + row * 128 + ((c ^ (row & 7)) << 4),
                 Abase + (size_t)row * HID + k0 + c * 4);
        }
        #pragma unroll
        for (int ii = 0; ii < 4; ++ii) {
            const int id = tid + ii * 256;
            const int row = id >> 3, c = id & 7;
            cp16(sB + row * 128 + ((c ^ (row & 7)) << 4),
                 Bbase + (size_t)row * HID + k0 + c * 4);
        }
    };

    auto compute = [&](int s) {
        const float* As = sm + s * STAGE_FLOATS;
        const float* Bs = As + TILE_FLOATS;
        #pragma unroll
        for (int half = 0; half < 2; ++half) {
            // A: rows wm+g, wm+8+g, wm+16+g, wm+24+g; atom (t*2+half)^g
            float4 a[4];
            #pragma unroll
            for (int r = 0; r < 4; ++r) {
                const int row = wm + r * 8 + g;
                a[r] = *(const float4*)(As + row * 32 + (((t * 2 + half) ^ g) << 2));
            }
            #pragma unroll
            for (int jc = 0; jc < 2; ++jc) {
                float4 b[4];
                #pragma unroll
                for (int jj = 0; jj < 4; ++jj) {
                    const int row = wn + (jc * 4 + jj) * 8 + g;
                    b[jj] = *(const float4*)(Bs + row * 32 + (((t * 2 + half) ^ g) << 2));
                }
                #pragma unroll
                for (int jj = 0; jj < 4; ++jj) {
                    const int j = jc * 4 + jj;
                    #pragma unroll
                    for (int i = 0; i < 2; i++) {
                        // kk = 16*half : A cols t, t+4 -> (x, y)
                        asm volatile(
                            "mma.sync.aligned.m16n8k8.row.col.f32.tf32.tf32.f32 "
                            "{%0,%1,%2,%3}, {%4,%5,%6,%7}, {%8,%9}, {%0,%1,%2,%3};\n"
                            : "+f"(acc[i][j][0]), "+f"(acc[i][j][1]),
                              "+f"(acc[i][j][2]), "+f"(acc[i][j][3])
                            : "r"(__float_as_uint(a[2*i].x)), "r"(__float_as_uint(a[2*i+1].x)),
                              "r"(__float_as_uint(a[2*i].y)), "r"(__float_as_uint(a[2*i+1].y)),
                              "r"(__float_as_uint(b[jj].x)),  "r"(__float_as_uint(b[jj].y)));
                        // kk = 16*half + 8 : A cols t, t+4 -> (z, w)
                        asm volatile(
                            "mma.sync.aligned.m16n8k8.row.col.f32.tf32.tf32.f32 "
                            "{%0,%1,%2,%3}, {%4,%5,%6,%7}, {%8,%9}, {%0,%1,%2,%3};\n"
                            : "+f"(acc[i][j][0]), "+f"(acc[i][j][1]),
                              "+f"(acc[i][j][2]), "+f"(acc[i][j][3])
                            : "r"(__float_as_uint(a[2*i].z)), "r"(__float_as_uint(a[2*i+1].z)),
                              "r"(__float_as_uint(a[2*i].w)), "r"(__float_as_uint(a[2*i+1].w)),
                              "r"(__float_as_uint(b[jj].z)),  "r"(__float_as_uint(b[jj].w)));
                    }
                }
            }
        }
    };

    const int nIter = HID / BK;   // 40
    fill(0, 0); CP_COMMIT();
    fill(1, 1); CP_COMMIT();

    for (int it = 0; it < nIter; ++it) {
        if (it + 2 < nIter) asm volatile("cp.async.wait_group 1;" ::: "memory");
        else                asm volatile("cp.async.wait_group 0;" ::: "memory");
        __syncthreads();
        if (it + 2 < nIter) {
            fill(it + 2, (it + 2) % NSTAGE);
            CP_COMMIT();
        }
        compute(it % NSTAGE);
    }

    // epilogue: bias + store
    #pragma unroll
    for (int i = 0; i < 2; i++) {
        #pragma unroll
        for (int j = 0; j < 8; j++) {
            const int r = block_m + wm + i * 16 + g;
            const int c = block_n + wn + j * 8 + t * 2;
            const float b0 = bias[c], b1 = bias[c + 1];
            float2 v0 = make_float2(acc[i][j][0] + b0, acc[i][j][1] + b1);
            float2 v1 = make_float2(acc[i][j][2] + b0, acc[i][j][3] + b1);
            *(float2*)&C[(size_t)r       * N + c] = v0;
            *(float2*)&C[(size_t)(r + 8) * N + c] = v1;
        }
    }
}

// ---------------------------------------------------------------------------
// RNA round + K-permute: one 32-float block per thread (rows are mult of 32)
// ---------------------------------------------------------------------------
__global__ void rna_perm(const float* __restrict__ in, float* __restrict__ out, int nblk)
{
    const int b = blockIdx.x * 256 + threadIdx.x;
    if (b >= nblk) return;
    const float* src = in + (size_t)b * 32;
    float v[32];
    #pragma unroll
    for (int i = 0; i < 8; ++i) {
        float4 f = *(const float4*)(src + i * 4);
        v[i * 4 + 0] = f.x; v[i * 4 + 1] = f.y; v[i * 4 + 2] = f.z; v[i * 4 + 3] = f.w;
    }
    float* dst = out + (size_t)b * 32;
    #pragma unroll
    for (int t = 0; t < 4; ++t) {
        float4 o0, o1;
        o0.x = __uint_as_float(f2tf32(v[t]));
        o0.y = __uint_as_float(f2tf32(v[4 + t]));
        o0.z = __uint_as_float(f2tf32(v[8 + t]));
        o0.w = __uint_as_float(f2tf32(v[12 + t]));
        o1.x = __uint_as_float(f2tf32(v[16 + t]));
        o1.y = __uint_as_float(f2tf32(v[20 + t]));
        o1.z = __uint_as_float(f2tf32(v[24 + t]));
        o1.w = __uint_as_float(f2tf32(v[28 + t]));
        *(float4*)(dst + t * 8)     = o0;
        *(float4*)(dst + t * 8 + 4) = o1;
    }
}

// ---------------------------------------------------------------------------
// Transpose + RNA + K-permute: in [K=1280][C] -> out [C][1280 permuted]
// ---------------------------------------------------------------------------
__global__ void transpose_perm_rna(const float* __restrict__ in, float* __restrict__ out, int C)
{
    __shared__ float tile[32][33];
    const int x  = blockIdx.x * 32 + threadIdx.x;   // col in input (n)
    const int y0 = blockIdx.y * 32;                  // k base
    #pragma unroll
    for (int j = threadIdx.y; j < 32; j += 8)
        tile[j][threadIdx.x] = in[(size_t)(y0 + j) * C + x];
    __syncthreads();
    const int k  = y0 + threadIdx.x;                 // k index after transpose
    const int n0 = blockIdx.x * 32;
    const int pk = permg(k);
    #pragma unroll
    for (int j = threadIdx.y; j < 32; j += 8)
        out[(size_t)(n0 + j) * HID + pk] = __uint_as_float(f2tf32(tile[threadIdx.x][j]));
}

// ---------------------------------------------------------------------------
// Windowed attention, one block per (window, head). Output stored RNA-rounded
// and K-permuted (it is gemm2's A operand).
// ---------------------------------------------------------------------------
#define QKV_STRIDE 81
#define P_STRIDE 65
#define ATTN_SMEM ((3 * 64 * QKV_STRIDE + 64 * P_STRIDE) * 4)

__global__ __launch_bounds__(128, 2)
void attn_win(const float* __restrict__ qkv,
              const float* __restrict__ cosp, const float* __restrict__ sinp,
              float* __restrict__ out)
{
    extern __shared__ float sh[];
    float* qs = sh;
    float* ks = sh + 64 * QKV_STRIDE;
    float* vs = sh + 2 * 64 * QKV_STRIDE;
    float* p  = sh + 3 * 64 * QKV_STRIDE;

    const int w = blockIdx.x >> 4;
    const int h = blockIdx.x & 15;
    const int tid = threadIdx.x;

    for (int idx = tid; idx < 64 * 40; idx += 128) {
        const int i = idx / 40;
        const int d = idx - i * 40;
        const int srow = w * WIN + i;
        const float c1 = cosp[srow * DHEAD + d];
        const float s1 = sinp[srow * DHEAD + d];
        const float c2 = cosp[srow * DHEAD + d + 40];
        const float s2 = sinp[srow * DHEAD + d + 40];
        const float* base = qkv + (size_t)srow * N_QKV + h * DHEAD;
        const float q1 = base[d],       q2 = base[d + 40];
        const float k1 = base[HID + d], k2 = base[HID + d + 40];
        qs[i * QKV_STRIDE + d]      = q1 * c1 - q2 * s1;
        qs[i * QKV_STRIDE + d + 40] = q2 * c2 + q1 * s2;
        ks[i * QKV_STRIDE + d]      = k1 * c1 - k2 * s1;
        ks[i * QKV_STRIDE + d + 40] = k2 * c2 + k1 * s2;
    }
    for (int idx = tid; idx < 64 * 80; idx += 128) {
        const int i = idx / 80;
        const int d = idx - i * 80;
        vs[i * QKV_STRIDE + d] = qkv[(size_t)(w * WIN + i) * N_QKV + 2 * HID + h * DHEAD + d];
    }
    __syncthreads();

    const int ti = tid >> 3;
    const int tj = tid & 7;
    const int i0 = ti * 4;
    const int j0 = tj * 8;
    float sc[4][8];
    #pragma unroll
    for (int r = 0; r < 4; r++)
        #pragma unroll
        for (int c = 0; c < 8; c++) sc[r][c] = 0.f;

    for (int d = 0; d < DHEAD; d++) {
        float qv[4], kv[8];
        #pragma unroll
        for (int r = 0; r < 4; r++) qv[r] = qs[(i0 + r) * QKV_STRIDE + d];
        #pragma unroll
        for (int c = 0; c < 8; c++) kv[c] = ks[(j0 + c) * QKV_STRIDE + d];
        #pragma unroll
        for (int r = 0; r < 4; r++)
            #pragma unroll
            for (int c = 0; c < 8; c++) sc[r][c] = fmaf(qv[r], kv[c], sc[r][c]);
    }
    const float scale = 0.11180339887498949f;
    #pragma unroll
    for (int r = 0; r < 4; r++)
        #pragma unroll
        for (int c = 0; c < 8; c++)
            p[(i0 + r) * P_STRIDE + j0 + c] = sc[r][c] * scale;
    __syncthreads();

    if (tid < 64) {
        float* row = p + tid * P_STRIDE;
        float m = -1e30f;
        #pragma unroll 8
        for (int j = 0; j < 64; j++) m = fmaxf(m, row[j]);
        float s = 0.f;
        #pragma unroll 8
        for (int j = 0; j < 64; j++) { float e = __expf(row[j] - m); row[j] = e; s += e; }
        const float inv = 1.f / s;
        #pragma unroll 8
        for (int j = 0; j < 64; j++) row[j] *= inv;
    }
    __syncthreads();

    const int tc = tid & 7;
    const int c0 = tc * 10;
    float o[4][10];
    #pragma unroll
    for (int r = 0; r < 4; r++)
        #pragma unroll
        for (int c = 0; c < 10; c++) o[r][c] = 0.f;

    for (int j = 0; j < 64; j++) {
        float pv[4], vv[10];
        #pragma unroll
        for (int r = 0; r < 4; r++) pv[r] = p[(i0 + r) * P_STRIDE + j];
        #pragma unroll
        for (int c = 0; c < 10; c++) vv[c] = vs[j * QKV_STRIDE + c0 + c];
        #pragma unroll
        for (int r = 0; r < 4; r++)
            #pragma unroll
            for (int c = 0; c < 10; c++) o[r][c] = fmaf(pv[r], vv[c], o[r][c]);
    }
    #pragma unroll
    for (int r = 0; r < 4; r++) {
        const size_t row = (size_t)(w * WIN + i0 + r) * HID;
        #pragma unroll
        for (int c = 0; c < 10; c++)
            out[row + permg(h * DHEAD + c0 + c)] = __uint_as_float(f2tf32(o[r][c]));
    }
}

// ---------------------------------------------------------------------------
extern "C" void kernel_launch(void* const* d_in, const int* in_sizes, int n_in,
                              void* d_out, int out_size)
{
    const float* x     = (const float*)d_in[0];
    const float* cosp  = (const float*)d_in[1];
    const float* sinp  = (const float*)d_in[2];
    const float* qkvW  = (const float*)d_in[4];
    const float* qkvB  = (const float*)d_in[5];
    const float* projW = (const float*)d_in[6];
    const float* projB = (const float*)d_in[7];
    float* out = (float*)d_out;

    float *xa, *qkv, *attn, *wqkvT, *wprojT;
    cudaGetSymbolAddress((void**)&xa,     g_xa);
    cudaGetSymbolAddress((void**)&qkv,    g_qkv);
    cudaGetSymbolAddress((void**)&attn,   g_attn);
    cudaGetSymbolAddress((void**)&wqkvT,  g_wqkvT);
    cudaGetSymbolAddress((void**)&wprojT, g_wprojT);

    cudaFuncSetAttribute(gemm_tc,  cudaFuncAttributeMaxDynamicSharedMemorySize, GEMM_SMEM);
    cudaFuncSetAttribute(attn_win, cudaFuncAttributeMaxDynamicSharedMemorySize, ATTN_SMEM);

    // Prepasses: RNA + K-permute x; transpose + RNA + K-permute weights
    rna_perm<<<(S_TOK * HID / 32 + 255) / 256, 256>>>(x, xa, S_TOK * HID / 32);
    {
        dim3 b(32, 8);
        transpose_perm_rna<<<dim3(N_QKV / 32, HID / 32), b>>>(qkvW, wqkvT, N_QKV);
        transpose_perm_rna<<<dim3(HID / 32, HID / 32), b>>>(projW, wprojT, HID);
    }
    // 1) QKV = x @ qkvW + b
    gemm_tc<<<dim3(N_QKV / BN, S_TOK / BM), 256, GEMM_SMEM>>>(xa, wqkvT, qkvB, qkv, N_QKV);
    // 2) windowed attention (RoPE fused)
    attn_win<<<NWIN * NHEAD, 128, ATTN_SMEM>>>(qkv, cosp, sinp, attn);
    // 3) out = attn @ projW + b
    gemm_tc<<<dim3(HID / BN, S_TOK / BM), 256, GEMM_SMEM>>>(attn, wprojT, projB, out, HID);
}

// round 6
// speedup vs baseline: 1.4331x; 1.4331x over previous
#include <cuda_runtime.h>
#include <cuda_fp16.h>
#include <cstdint>

// Problem constants
#define S_TOK   32768
#define HID     1280
#define NHEAD   16
#define DHEAD   80
#define WIN     64
#define NWIN    (S_TOK / WIN)
#define N_QKV   (3 * HID)

// Scratch (__device__ globals per allocation rules)
__device__ __half g_xh    [(size_t)S_TOK * HID];    // x -> fp16
__device__ float  g_qkv   [(size_t)S_TOK * N_QKV];  // qkv output fp32
__device__ __half g_attnh [(size_t)S_TOK * HID];    // attn out -> fp16
__device__ __half g_wqkvT [(size_t)N_QKV * HID];    // qkvW^T  [3840,1280] fp16
__device__ __half g_wprojT[(size_t)HID * HID];      // projW^T [1280,1280] fp16

__device__ __forceinline__ uint32_t smem_u32(const void* p) {
    uint32_t a;
    asm("{ .reg .u64 t; cvta.to.shared.u64 t, %1; cvt.u32.u64 %0, t; }" : "=r"(a) : "l"(p));
    return a;
}
__device__ __forceinline__ void cp16(uint32_t dst, const void* src) {
    asm volatile("cp.async.cg.shared.global [%0], [%1], 16;" :: "r"(dst), "l"(src) : "memory");
}
#define CP_COMMIT() asm volatile("cp.async.commit_group;" ::: "memory")

// ---------------------------------------------------------------------------
// fp16 tensor-core GEMM: C[M,N] = A[M,1280] @ Bt[N,1280]^T + bias[N]  (fp32 acc)
// A, Bt row-major fp16. Block 128x128x32, 8 warps (4M x 2N, warp tile 32x64),
// 3-stage cp.async pipeline, ONE __syncthreads per K-iteration.
// Row stride 40 halves (80B): g*20+t mod 32 bijective -> conflict-free LDS.32.
// ---------------------------------------------------------------------------
#define BM 128
#define BN 128
#define BK 32
#define NSTAGE 3
#define ROW_H 40                               // halves per smem row (32 + 8 pad)
#define TILE_HALVES (128 * ROW_H)              // 5120
#define STAGE_HALVES (2 * TILE_HALVES)         // 10240
#define GEMM_SMEM (NSTAGE * STAGE_HALVES * 2)  // 61440 B

__global__ __launch_bounds__(256, 2)
void gemm_h(const __half* __restrict__ A, const __half* __restrict__ Bt,
            const float* __restrict__ bias, float* __restrict__ C, int N)
{
    extern __shared__ __half smh[];
    const int tid  = threadIdx.x;
    const int warp = tid >> 5;
    const int lane = tid & 31;
    const int g = lane >> 2;       // 0..7
    const int t = lane & 3;        // 0..3
    const int wm = (warp & 3) * 32;
    const int wn = (warp >> 2) * 64;
    const int block_m = blockIdx.y * BM;
    const int block_n = blockIdx.x * BN;

    const uint32_t sb = smem_u32(smh);

    float acc[2][8][4];
    #pragma unroll
    for (int i = 0; i < 2; i++)
        #pragma unroll
        for (int j = 0; j < 8; j++)
            #pragma unroll
            for (int r = 0; r < 4; r++) acc[i][j][r] = 0.f;

    const __half* Abase = A  + (size_t)block_m * HID;
    const __half* Bbase = Bt + (size_t)block_n * HID;

    // fill stage s with K-chunk kidx: A/B each 128 rows x 4 chunks of 16B
    auto fill = [&](int kidx, int s) {
        const uint32_t sA = sb + s * STAGE_HALVES * 2;
        const uint32_t sB = sA + TILE_HALVES * 2;
        const int k0 = kidx * BK;
        #pragma unroll
        for (int ii = 0; ii < 2; ++ii) {
            const int id = tid + ii * 256;
            const int row = id >> 2, c = id & 3;
            cp16(sA + row * (ROW_H * 2) + c * 16,
                 Abase + (size_t)row * HID + k0 + c * 8);
        }
        #pragma unroll
        for (int ii = 0; ii < 2; ++ii) {
            const int id = tid + ii * 256;
            const int row = id >> 2, c = id & 3;
            cp16(sB + row * (ROW_H * 2) + c * 16,
                 Bbase + (size_t)row * HID + k0 + c * 8);
        }
    };

    auto compute = [&](int s) {
        const __half* As = smh + s * STAGE_HALVES;
        const __half* Bs = As + TILE_HALVES;
        #pragma unroll
        for (int ks = 0; ks < 2; ++ks) {           // k base = ks*16
            const int kb = ks * 16 + 2 * t;
            uint32_t af[2][4];
            #pragma unroll
            for (int i = 0; i < 2; i++) {
                const int r0 = wm + i * 16 + g;
                af[i][0] = *(const uint32_t*)(As + r0       * ROW_H + kb);
                af[i][1] = *(const uint32_t*)(As + (r0 + 8) * ROW_H + kb);
                af[i][2] = *(const uint32_t*)(As + r0       * ROW_H + kb + 8);
                af[i][3] = *(const uint32_t*)(As + (r0 + 8) * ROW_H + kb + 8);
            }
            uint32_t bf[8][2];
            #pragma unroll
            for (int j = 0; j < 8; j++) {
                const int rb = wn + j * 8 + g;
                bf[j][0] = *(const uint32_t*)(Bs + rb * ROW_H + kb);
                bf[j][1] = *(const uint32_t*)(Bs + rb * ROW_H + kb + 8);
            }
            #pragma unroll
            for (int i = 0; i < 2; i++)
                #pragma unroll
                for (int j = 0; j < 8; j++) {
                    asm volatile(
                        "mma.sync.aligned.m16n8k16.row.col.f32.f16.f16.f32 "
                        "{%0,%1,%2,%3}, {%4,%5,%6,%7}, {%8,%9}, {%0,%1,%2,%3};\n"
                        : "+f"(acc[i][j][0]), "+f"(acc[i][j][1]),
                          "+f"(acc[i][j][2]), "+f"(acc[i][j][3])
                        : "r"(af[i][0]), "r"(af[i][1]), "r"(af[i][2]), "r"(af[i][3]),
                          "r"(bf[j][0]), "r"(bf[j][1]));
                }
        }
    };

    const int nIter = HID / BK;   // 40
    fill(0, 0); CP_COMMIT();
    fill(1, 1); CP_COMMIT();

    for (int it = 0; it < nIter; ++it) {
        if (it + 2 < nIter) asm volatile("cp.async.wait_group 1;" ::: "memory");
        else                asm volatile("cp.async.wait_group 0;" ::: "memory");
        __syncthreads();     // stage it%NSTAGE ready; stage (it+2)%NSTAGE free
        if (it + 2 < nIter) {
            fill(it + 2, (it + 2) % NSTAGE);
            CP_COMMIT();
        }
        compute(it % NSTAGE);
    }

    // epilogue: bias + fp32 store
    #pragma unroll
    for (int i = 0; i < 2; i++) {
        #pragma unroll
        for (int j = 0; j < 8; j++) {
            const int r = block_m + wm + i * 16 + g;
            const int c = block_n + wn + j * 8 + t * 2;
            const float b0 = bias[c], b1 = bias[c + 1];
            float2 v0 = make_float2(acc[i][j][0] + b0, acc[i][j][1] + b1);
            float2 v1 = make_float2(acc[i][j][2] + b0, acc[i][j][3] + b1);
            *(float2*)&C[(size_t)r       * N + c] = v0;
            *(float2*)&C[(size_t)(r + 8) * N + c] = v1;
        }
    }
}

// ---------------------------------------------------------------------------
// fp32 -> fp16 convert (vectorized)
// ---------------------------------------------------------------------------
__global__ void f32_to_f16(const float4* __restrict__ in, uint2* __restrict__ out, int n4)
{
    const int i = blockIdx.x * 256 + threadIdx.x;
    if (i < n4) {
        float4 v = in[i];
        __half2 h0 = __floats2half2_rn(v.x, v.y);
        __half2 h1 = __floats2half2_rn(v.z, v.w);
        uint2 r;
        r.x = *(uint32_t*)&h0;
        r.y = *(uint32_t*)&h1;
        out[i] = r;
    }
}

// ---------------------------------------------------------------------------
// Transpose + fp16: in f32 [K=1280][C] -> out fp16 [C][1280]
// ---------------------------------------------------------------------------
__global__ void transpose_f16(const float* __restrict__ in, __half* __restrict__ out, int C)
{
    __shared__ float tile[32][33];
    const int x  = blockIdx.x * 32 + threadIdx.x;   // col in input (n)
    const int y0 = blockIdx.y * 32;                  // k base
    #pragma unroll
    for (int j = threadIdx.y; j < 32; j += 8)
        tile[j][threadIdx.x] = in[(size_t)(y0 + j) * C + x];
    __syncthreads();
    const int k  = y0 + threadIdx.x;
    const int n0 = blockIdx.x * 32;
    #pragma unroll
    for (int j = threadIdx.y; j < 32; j += 8)
        out[(size_t)(n0 + j) * HID + k] = __float2half_rn(tile[threadIdx.x][j]);
}

// ---------------------------------------------------------------------------
// Windowed attention, one block per (window, head). Output stored fp16
// (it is gemm2's A operand). fp32 math inside.
// ---------------------------------------------------------------------------
#define QKV_STRIDE 81
#define P_STRIDE 65
#define ATTN_SMEM ((3 * 64 * QKV_STRIDE + 64 * P_STRIDE) * 4)

__global__ __launch_bounds__(128, 2)
void attn_win(const float* __restrict__ qkv,
              const float* __restrict__ cosp, const float* __restrict__ sinp,
              __half* __restrict__ out)
{
    extern __shared__ float sh[];
    float* qs = sh;
    float* ks = sh + 64 * QKV_STRIDE;
    float* vs = sh + 2 * 64 * QKV_STRIDE;
    float* p  = sh + 3 * 64 * QKV_STRIDE;

    const int w = blockIdx.x >> 4;
    const int h = blockIdx.x & 15;
    const int tid = threadIdx.x;

    for (int idx = tid; idx < 64 * 40; idx += 128) {
        const int i = idx / 40;
        const int d = idx - i * 40;
        const int srow = w * WIN + i;
        const float c1 = cosp[srow * DHEAD + d];
        const float s1 = sinp[srow * DHEAD + d];
        const float c2 = cosp[srow * DHEAD + d + 40];
        const float s2 = sinp[srow * DHEAD + d + 40];
        const float* base = qkv + (size_t)srow * N_QKV + h * DHEAD;
        const float q1 = base[d],       q2 = base[d + 40];
        const float k1 = base[HID + d], k2 = base[HID + d + 40];
        qs[i * QKV_STRIDE + d]      = q1 * c1 - q2 * s1;
        qs[i * QKV_STRIDE + d + 40] = q2 * c2 + q1 * s2;
        ks[i * QKV_STRIDE + d]      = k1 * c1 - k2 * s1;
        ks[i * QKV_STRIDE + d + 40] = k2 * c2 + k1 * s2;
    }
    for (int idx = tid; idx < 64 * 80; idx += 128) {
        const int i = idx / 80;
        const int d = idx - i * 80;
        vs[i * QKV_STRIDE + d] = qkv[(size_t)(w * WIN + i) * N_QKV + 2 * HID + h * DHEAD + d];
    }
    __syncthreads();

    const int ti = tid >> 3;
    const int tj = tid & 7;
    const int i0 = ti * 4;
    const int j0 = tj * 8;
    float sc[4][8];
    #pragma unroll
    for (int r = 0; r < 4; r++)
        #pragma unroll
        for (int c = 0; c < 8; c++) sc[r][c] = 0.f;

    for (int d = 0; d < DHEAD; d++) {
        float qv[4], kv[8];
        #pragma unroll
        for (int r = 0; r < 4; r++) qv[r] = qs[(i0 + r) * QKV_STRIDE + d];
        #pragma unroll
        for (int c = 0; c < 8; c++) kv[c] = ks[(j0 + c) * QKV_STRIDE + d];
        #pragma unroll
        for (int r = 0; r < 4; r++)
            #pragma unroll
            for (int c = 0; c < 8; c++) sc[r][c] = fmaf(qv[r], kv[c], sc[r][c]);
    }
    const float scale = 0.11180339887498949f;
    #pragma unroll
    for (int r = 0; r < 4; r++)
        #pragma unroll
        for (int c = 0; c < 8; c++)
            p[(i0 + r) * P_STRIDE + j0 + c] = sc[r][c] * scale;
    __syncthreads();

    if (tid < 64) {
        float* row = p + tid * P_STRIDE;
        float m = -1e30f;
        #pragma unroll 8
        for (int j = 0; j < 64; j++) m = fmaxf(m, row[j]);
        float s = 0.f;
        #pragma unroll 8
        for (int j = 0; j < 64; j++) { float e = __expf(row[j] - m); row[j] = e; s += e; }
        const float inv = 1.f / s;
        #pragma unroll 8
        for (int j = 0; j < 64; j++) row[j] *= inv;
    }
    __syncthreads();

    const int tc = tid & 7;
    const int c0 = tc * 10;
    float o[4][10];
    #pragma unroll
    for (int r = 0; r < 4; r++)
        #pragma unroll
        for (int c = 0; c < 10; c++) o[r][c] = 0.f;

    for (int j = 0; j < 64; j++) {
        float pv[4], vv[10];
        #pragma unroll
        for (int r = 0; r < 4; r++) pv[r] = p[(i0 + r) * P_STRIDE + j];
        #pragma unroll
        for (int c = 0; c < 10; c++) vv[c] = vs[j * QKV_STRIDE + c0 + c];
        #pragma unroll
        for (int r = 0; r < 4; r++)
            #pragma unroll
            for (int c = 0; c < 10; c++) o[r][c] = fmaf(pv[r], vv[c], o[r][c]);
    }
    #pragma unroll
    for (int r = 0; r < 4; r++) {
        const size_t row = (size_t)(w * WIN + i0 + r) * HID + h * DHEAD + c0;
        #pragma unroll
        for (int c = 0; c < 10; c++)
            out[row + c] = __float2half_rn(o[r][c]);   // fp16: feeds GEMM2
    }
}

// ---------------------------------------------------------------------------
extern "C" void kernel_launch(void* const* d_in, const int* in_sizes, int n_in,
                              void* d_out, int out_size)
{
    const float* x     = (const float*)d_in[0];
    const float* cosp  = (const float*)d_in[1];
    const float* sinp  = (const float*)d_in[2];
    const float* qkvW  = (const float*)d_in[4];
    const float* qkvB  = (const float*)d_in[5];
    const float* projW = (const float*)d_in[6];
    const float* projB = (const float*)d_in[7];
    float* out = (float*)d_out;

    __half *xh, *attnh, *wqkvT, *wprojT;
    float *qkv;
    cudaGetSymbolAddress((void**)&xh,     g_xh);
    cudaGetSymbolAddress((void**)&qkv,    g_qkv);
    cudaGetSymbolAddress((void**)&attnh,  g_attnh);
    cudaGetSymbolAddress((void**)&wqkvT,  g_wqkvT);
    cudaGetSymbolAddress((void**)&wprojT, g_wprojT);

    cudaFuncSetAttribute(gemm_h,   cudaFuncAttributeMaxDynamicSharedMemorySize, GEMM_SMEM);
    cudaFuncSetAttribute(attn_win, cudaFuncAttributeMaxDynamicSharedMemorySize, ATTN_SMEM);

    // Prepasses: x -> fp16; weights -> transpose + fp16
    f32_to_f16<<<(S_TOK * HID / 4 + 255) / 256, 256>>>((const float4*)x, (uint2*)xh, S_TOK * HID / 4);
    {
        dim3 b(32, 8);
        transpose_f16<<<dim3(N_QKV / 32, HID / 32), b>>>(qkvW, wqkvT, N_QKV);
        transpose_f16<<<dim3(HID / 32, HID / 32), b>>>(projW, wprojT, HID);
    }
    // 1) QKV = x @ qkvW + b
    gemm_h<<<dim3(N_QKV / BN, S_TOK / BM), 256, GEMM_SMEM>>>(xh, wqkvT, qkvB, qkv, N_QKV);
    // 2) windowed attention (RoPE fused)
    attn_win<<<NWIN * NHEAD, 128, ATTN_SMEM>>>(qkv, cosp, sinp, attnh);
    // 3) out = attn @ projW + b
    gemm_h<<<dim3(HID / BN, S_TOK / BM), 256, GEMM_SMEM>>>(attnh, wprojT, projB, out, HID);
}